// round 16
// baseline (speedup 1.0000x reference)
#include <cuda_runtime.h>
#include <cuda_fp16.h>
#include <cstdint>

// ---------------- problem constants ----------------
#define T_TOK   8192
#define D_MODEL 1024
#define D_COND  256
#define D_IN    1280      // D_MODEL + D_COND
#define D_FF    4096
#define NEXP    8
#define TOPK    2
#define CAP     2560      // int(1.25 * 2 * 8192 / 8)
#define TKA     (T_TOK*TOPK)

typedef __half h16;

// ---------------- device scratch (static, no runtime allocation) ----------------
__device__ int   g_expert[TKA];
__device__ float g_weight[TKA];
__device__ int   g_slot[TKA];
__device__ int   g_route[NEXP*CAP];
__device__ int   g_cnt[NEXP];
__device__ float g_Y[(size_t)NEXP * CAP * D_MODEL];     // expert output (fp32)
__device__ h16 g_xh[(size_t)T_TOK * D_IN];              // fp16 [x|cond]
__device__ h16 g_Hsh[(size_t)T_TOK * D_FF];             // fp16 shared hidden
__device__ h16 g_Heh[(size_t)NEXP * CAP * D_FF];        // fp16 expert hidden
__device__ h16 g_W1sT[(size_t)D_FF * D_IN];             // fp16 W^T  [N][K]
__device__ h16 g_W2sT[(size_t)D_MODEL * D_FF];
__device__ h16 g_W1eT[(size_t)NEXP * D_FF * D_IN];
__device__ h16 g_W2eT[(size_t)NEXP * D_MODEL * D_FF];

// ---------------- helpers ----------------
__device__ __forceinline__ void cp16(void* dst_smem, const void* src_gmem) {
    unsigned sa = (unsigned)__cvta_generic_to_shared(dst_smem);
    asm volatile("cp.async.cg.shared.global [%0], [%1], 16;" :: "r"(sa), "l"(src_gmem));
}
__device__ __forceinline__ float gelu_f(float v) {
    // jax.nn.gelu (tanh form), HW tanh.approx
    float u = 0.7978845608028654f * (v + 0.044715f * v * v * v);
    float t;
    asm("tanh.approx.f32 %0, %1;" : "=f"(t) : "f"(u));
    return 0.5f * v * (1.0f + t);
}
#define MMA_F16(d, a, b) \
    asm volatile( \
        "mma.sync.aligned.m16n8k16.row.col.f32.f16.f16.f32 " \
        "{%0,%1,%2,%3}, {%4,%5,%6,%7}, {%8,%9}, {%0,%1,%2,%3};" \
        : "+f"((d)[0]), "+f"((d)[1]), "+f"((d)[2]), "+f"((d)[3]) \
        : "r"((a)[0]), "r"((a)[1]), "r"((a)[2]), "r"((a)[3]), \
          "r"((b)[0]), "r"((b)[1]))

// ---------------- 0) prep: fused pack(x|cond->fp16) + transpose(all W -> fp16 [C][R]) ----
#define PACK_BLOCKS 10240
__global__ __launch_bounds__(256) void prep_kernel(const float* __restrict__ x,
                                                   const float* __restrict__ cond,
                                                   const float* __restrict__ W1s,
                                                   const float* __restrict__ W2s,
                                                   const float* __restrict__ W1e,
                                                   const float* __restrict__ W2e) {
    __shared__ float t[32][129];
    const int tid = threadIdx.x;
    int bid = blockIdx.x;

    if (bid < PACK_BLOCKS) {
        int i = bid * 256 + tid;               // float4 index; 320 per row
        int tok = i / 320, c4 = i % 320;
        float4 v;
        if (c4 < 256) v = ((const float4*)x)[(size_t)tok * 256 + c4];
        else          v = ((const float4*)cond)[(size_t)tok * 64 + (c4 - 256)];
        __half2 a = __floats2half2_rn(v.x, v.y);
        __half2 b = __floats2half2_rn(v.z, v.w);
        uint2 u = make_uint2(*(unsigned*)&a, *(unsigned*)&b);
        *(uint2*)(g_xh + (size_t)tok * D_IN + c4 * 4) = u;
        return;
    }
    bid -= PACK_BLOCKS;

    const float* src; h16* dst; int R, C;
    if (bid < 1280) {
        src = W1s; dst = g_W1sT; R = D_IN; C = D_FF;
    } else if (bid < 2304) {
        bid -= 1280; src = W2s; dst = g_W2sT; R = D_FF; C = D_MODEL;
    } else if (bid < 12544) {
        bid -= 2304; int e = bid / 1280; bid %= 1280;
        src = W1e + (size_t)e * D_IN * D_FF; dst = g_W1eT + (size_t)e * D_IN * D_FF;
        R = D_IN; C = D_FF;
    } else {
        bid -= 12544; int e = bid / 1024; bid %= 1024;
        src = W2e + (size_t)e * D_FF * D_MODEL; dst = g_W2eT + (size_t)e * D_FF * D_MODEL;
        R = D_FF; C = D_MODEL;
    }
    int tilesx = C / 128;
    int c0 = (bid % tilesx) * 128, r0 = (bid / tilesx) * 32;

    int row = tid >> 3, cq = tid & 7;
#pragma unroll
    for (int j = 0; j < 4; j++) {
        int c4i = (cq + 8 * j) * 4;
        float4 v = *(const float4*)(src + (size_t)(r0 + row) * C + c0 + c4i);
        t[row][c4i + 0] = v.x; t[row][c4i + 1] = v.y;
        t[row][c4i + 2] = v.z; t[row][c4i + 3] = v.w;
    }
    __syncthreads();

    int tx = tid & 31, iy = tid >> 5;
#pragma unroll
    for (int c = 0; c < 16; c++) {
        int i = iy + 8 * c;
        dst[(size_t)(c0 + i) * R + r0 + tx] = __float2half_rn(t[tx][i]);
    }
}

// ---------------- 1) router ----------------
__global__ __launch_bounds__(256) void router_kernel(const float* __restrict__ x,
                                                     const float* __restrict__ Wr) {
    __shared__ float sWr[D_MODEL * NEXP];
    const int tid = threadIdx.x;
    for (int i = tid; i < D_MODEL * NEXP; i += 256) sWr[i] = Wr[i];
    __syncthreads();

    const int warp = tid >> 5, lane = tid & 31;
    const int t = blockIdx.x * 8 + warp;
    const float* xr = x + (size_t)t * D_MODEL;

    float acc[NEXP];
#pragma unroll
    for (int e = 0; e < NEXP; e++) acc[e] = 0.f;
    for (int j = lane; j < D_MODEL; j += 32) {
        float xv = xr[j];
        const float* wrow = sWr + j * NEXP;
#pragma unroll
        for (int e = 0; e < NEXP; e++) acc[e] += xv * wrow[e];
    }
#pragma unroll
    for (int e = 0; e < NEXP; e++)
#pragma unroll
        for (int o = 16; o > 0; o >>= 1) acc[e] += __shfl_xor_sync(0xffffffffu, acc[e], o);

    if (lane == 0) {
        float mx = acc[0];
#pragma unroll
        for (int e = 1; e < NEXP; e++) mx = fmaxf(mx, acc[e]);
        float p[NEXP];
#pragma unroll
        for (int e = 0; e < NEXP; e++) p[e] = expf(acc[e] - mx);
        int i1 = 0; float v1 = p[0];
#pragma unroll
        for (int e = 1; e < NEXP; e++) if (p[e] > v1) { v1 = p[e]; i1 = e; }
        int i2 = -1; float v2 = -1.f;
#pragma unroll
        for (int e = 0; e < NEXP; e++) if (e != i1 && p[e] > v2) { v2 = p[e]; i2 = e; }
        float inv = 1.f / (v1 + v2);   // softmax denom cancels in normalization
        g_expert[2 * t]     = i1;  g_weight[2 * t]     = v1 * inv;
        g_expert[2 * t + 1] = i2;  g_weight[2 * t + 1] = v2 * inv;
    }
}

// ---------------- 2) binning: R12 semantics, packed-u64 counters ----------------
__global__ __launch_bounds__(512) void binning_kernel() {
    __shared__ int scnt[512 * NEXP];
    const int tid = threadIdx.x;
    for (int i = tid; i < NEXP * CAP; i += 512) g_route[i] = 0;

    const int base = tid * 32;           // 32 assignments per thread
    uint64_t c64 = 0;                    // 8 x 8-bit per-expert counters
#pragma unroll
    for (int i = 0; i < 32; i += 4) {
        int4 v = *(const int4*)(g_expert + base + i);
        c64 += (1ull << (v.x * 8)) + (1ull << (v.y * 8))
             + (1ull << (v.z * 8)) + (1ull << (v.w * 8));
    }
#pragma unroll
    for (int e = 0; e < NEXP; e++)
        scnt[tid * NEXP + e] = (int)((c64 >> (e * 8)) & 0xffull);
    __syncthreads();

    if (tid < NEXP) {
        int run = 0;
        for (int i = 0; i < 512; i++) {
            int v = scnt[i * NEXP + tid];
            scnt[i * NEXP + tid] = run;
            run += v;
        }
        g_cnt[tid] = min(run, CAP);
    }
    __syncthreads();

    uint64_t d64 = 0;
#pragma unroll
    for (int i = 0; i < 32; i += 4) {
        int4 v = *(const int4*)(g_expert + base + i);
        int es[4] = { v.x, v.y, v.z, v.w };
#pragma unroll
        for (int s = 0; s < 4; s++) {
            int e = es[s];
            int a = base + i + s;
            int pos = scnt[tid * NEXP + e] + (int)((d64 >> (e * 8)) & 0xffull);
            d64 += 1ull << (e * 8);
            if (pos < CAP) {
                int slot = e * CAP + pos;
                g_route[slot] = a >> 1;
                g_slot[a] = slot;
            } else {
                g_slot[a] = -1;
            }
        }
    }
}

// ---------------- 3) merged FP16 GEMM: 256 threads, 2x4 warp grid, 64x32 warp tile ----
// L1=true : y<64 -> Hs = fp16(gelu(xc @ W1s)) ; y>=64 -> He = fp16(gelu(gather @ W1e))
// L1=false: y<64 -> out = mask/3 * (Hs @ W2s) ; y>=64 -> Y = He @ W2e
// 128x128 CTA tile, BK=32, 3-stage cp.async, 1 barrier/k-tile, 2 CTAs/SM (16 warps).
#define STRB 40                      // smem row stride in halfs (32 data + 8 pad = 80B)
#define PLANE (128 * STRB)           // 5120 halfs = 10240 B
#define STAGE_ELE (2 * PLANE)        // A, B
#define STAGES 3
template <bool L1>
__global__ __launch_bounds__(256, 2) void gemm_kernel(const float* __restrict__ mask,
                                                      float* __restrict__ out) {
    constexpr int BM = 128, BK = 32;
    constexpr int KDIM = L1 ? D_IN : D_FF;
    constexpr int KT   = KDIM / BK;

    extern __shared__ h16 smem[];

    const int tid = threadIdx.x;
    const int n0 = blockIdx.x * 128;

    // ---- y-decode: shared tiles first, then expert tiles ----
    const int y = blockIdx.y;
    const bool sh = (y < 64);
    int e = 0, m0;
    if (sh) {
        m0 = y * BM;
    } else {
        int t = y - 64;
        e = t / 20;                      // 20 M-tiles per expert (CAP/128)
        m0 = (t % 20) * BM;
        if (m0 >= g_cnt[e]) return;      // uniform skip of empty tiles
    }

    const h16 *Ah, *Wh;
    if (L1) {
        Ah = g_xh;
        Wh = sh ? g_W1sT : (g_W1eT + (size_t)e * D_IN * D_FF);
    } else {
        Ah = sh ? g_Hsh : (g_Heh + (size_t)e * CAP * D_FF);
        Wh = sh ? g_W2sT : (g_W2eT + (size_t)e * D_FF * D_MODEL);
    }

    // ---- loader geometry (256 thr): chunk (tid&3)*16B, row group tid>>2 (+64*i) ----
    const int chunk = tid & 3;
    const int rg    = tid >> 2;          // 0..63

    size_t aoff[2], boff[2];
#pragma unroll
    for (int i = 0; i < 2; i++) {
        int r = rg + 64 * i;
        int arow = (L1 && !sh) ? g_route[e * CAP + m0 + r] : (m0 + r);
        aoff[i] = (size_t)arow * KDIM + chunk * 8;
        boff[i] = (size_t)(n0 + r) * KDIM + chunk * 8;
    }

    auto load_tile = [&](int kt, int st) {
        const int k0 = kt * BK;
        h16* s = smem + st * STAGE_ELE;
#pragma unroll
        for (int i = 0; i < 2; i++) {
            int d = (rg + 64 * i) * STRB + chunk * 8;
            cp16(s + d,         Ah + aoff[i] + k0);
            cp16(s + PLANE + d, Wh + boff[i] + k0);
        }
        asm volatile("cp.async.commit_group;" ::: "memory");
    };

    const int warp = tid >> 5, lane = tid & 31;
    const int wm = warp >> 2, wn = warp & 3;   // 2x4 warp grid; warp tile 64x32
    const int lr = lane >> 2, lc = lane & 3;   // groupID, threadID-in-group

    float acc[4][4][4];
#pragma unroll
    for (int f = 0; f < 4; f++)
#pragma unroll
        for (int g = 0; g < 4; g++)
#pragma unroll
            for (int c = 0; c < 4; c++) acc[f][g][c] = 0.f;

    // u32-unit fragment bases (half index / 2); row stride = STRB/2 = 20 u32
    const int a_u32 = ((wm * 64 + lr) * STRB) / 2 + lc;
    const int b_u32 = ((wn * 32 + lr) * STRB) / 2 + lc;

    load_tile(0, 0);
    load_tile(1, 1);

    int cur = 0, nxt = 2;                  // slot of tile kt; slot for tile kt+2
    for (int kt = 0; kt < KT; kt++) {
        if (kt + 1 < KT) {
            asm volatile("cp.async.wait_group 1;" ::: "memory");
        } else {
            asm volatile("cp.async.wait_group 0;" ::: "memory");
        }
        __syncthreads();                   // tile kt visible; slot `nxt` fully drained
        if (kt + 2 < KT) load_tile(kt + 2, nxt);

        const uint32_t* pA = (const uint32_t*)(smem + cur * STAGE_ELE);
        const uint32_t* pB = pA + PLANE / 2;

#pragma unroll
        for (int q = 0; q < 2; q++) {             // two k16 chunks per k-tile
            const int kq = q * 8;                 // u32 offset along k
            unsigned ah[4][4], bh[4][2];
#pragma unroll
            for (int f = 0; f < 4; f++) {
                const uint32_t* p = pA + a_u32 + f * 16 * (STRB / 2) + kq;
                ah[f][0] = p[0];
                ah[f][1] = p[8 * (STRB / 2)];
                ah[f][2] = p[4];
                ah[f][3] = p[8 * (STRB / 2) + 4];
            }
#pragma unroll
            for (int g = 0; g < 4; g++) {
                const uint32_t* p = pB + b_u32 + g * 8 * (STRB / 2) + kq;
                bh[g][0] = p[0];
                bh[g][1] = p[4];
            }
#pragma unroll
            for (int f = 0; f < 4; f++)
#pragma unroll
                for (int g = 0; g < 4; g++) MMA_F16(acc[f][g], ah[f], bh[g]);
        }
        cur = (cur == STAGES - 1) ? 0 : cur + 1;
        nxt = (nxt == STAGES - 1) ? 0 : nxt + 1;
    }

    // ---- epilogue ----
#pragma unroll
    for (int f = 0; f < 4; f++) {
        const int row = m0 + wm * 64 + f * 16 + lr;   // +8 for c2/c3
#pragma unroll
        for (int g = 0; g < 4; g++) {
            const int col = n0 + wn * 32 + g * 8 + 2 * lc;
            if (L1) {
                h16* dh = sh ? g_Hsh : (g_Heh + (size_t)e * CAP * D_FF);
                __half2 v0 = __floats2half2_rn(gelu_f(acc[f][g][0]), gelu_f(acc[f][g][1]));
                __half2 v1 = __floats2half2_rn(gelu_f(acc[f][g][2]), gelu_f(acc[f][g][3]));
                *(__half2*)(dh + (size_t)row * D_FF + col) = v0;
                *(__half2*)(dh + (size_t)(row + 8) * D_FF + col) = v1;
            } else if (sh) {
                float mk0 = mask[row] * (1.f / 3.f);
                float mk1 = mask[row + 8] * (1.f / 3.f);
                float2 v0 = make_float2(acc[f][g][0] * mk0, acc[f][g][1] * mk0);
                float2 v1 = make_float2(acc[f][g][2] * mk1, acc[f][g][3] * mk1);
                *(float2*)(out + (size_t)row * D_MODEL + col) = v0;
                *(float2*)(out + (size_t)(row + 8) * D_MODEL + col) = v1;
            } else {
                float* dst = g_Y + ((size_t)e * CAP + row) * D_MODEL;
                *(float2*)(dst + col) = make_float2(acc[f][g][0], acc[f][g][1]);
                *(float2*)(dst + (size_t)8 * D_MODEL + col) = make_float2(acc[f][g][2], acc[f][g][3]);
            }
        }
    }
}

// ---------------- 4) combine: out += (2/3)*mask*(w0*Y[s0] + w1*Y[s1]) ----------------
__global__ __launch_bounds__(256) void combine_kernel(const float* __restrict__ mask,
                                                      float* __restrict__ out) {
    const int idx = blockIdx.x * 256 + threadIdx.x;
    const int t = idx >> 8;
    const int c = (idx & 255) * 4;
    const int s0 = g_slot[2 * t], s1 = g_slot[2 * t + 1];
    const float w0 = g_weight[2 * t], w1 = g_weight[2 * t + 1];
    const float m = mask[t] * (2.f / 3.f);
    float ax = 0.f, ay = 0.f, az = 0.f, aw = 0.f;
    if (s0 >= 0) {
        float4 y = *(const float4*)(g_Y + (size_t)s0 * D_MODEL + c);
        ax += w0 * y.x; ay += w0 * y.y; az += w0 * y.z; aw += w0 * y.w;
    }
    if (s1 >= 0) {
        float4 y = *(const float4*)(g_Y + (size_t)s1 * D_MODEL + c);
        ax += w1 * y.x; ay += w1 * y.y; az += w1 * y.z; aw += w1 * y.w;
    }
    float4 o = *(float4*)(out + (size_t)t * D_MODEL + c);
    o.x += m * ax; o.y += m * ay; o.z += m * az; o.w += m * aw;
    *(float4*)(out + (size_t)t * D_MODEL + c) = o;
}

// ---------------- launch ----------------
extern "C" void kernel_launch(void* const* d_in, const int* in_sizes, int n_in,
                              void* d_out, int out_size) {
    const float* x    = (const float*)d_in[0];
    const float* cond = (const float*)d_in[1];
    const float* mask = (const float*)d_in[2];
    const float* Wr   = (const float*)d_in[3];
    const float* W1s  = (const float*)d_in[4];
    const float* W2s  = (const float*)d_in[5];
    const float* W1e  = (const float*)d_in[6];
    const float* W2e  = (const float*)d_in[7];
    float* out = (float*)d_out;

    const int smem = STAGES * STAGE_ELE * (int)sizeof(h16);   // 61440 B
    cudaFuncSetAttribute(gemm_kernel<true>,  cudaFuncAttributeMaxDynamicSharedMemorySize, smem);
    cudaFuncSetAttribute(gemm_kernel<false>, cudaFuncAttributeMaxDynamicSharedMemorySize, smem);

    // 3 launches before the GEMMs -> gemm<true> is this process's 4th launch (ncu slot)
    prep_kernel<<<30976, 256>>>(x, cond, W1s, W2s, W1e, W2e);
    router_kernel<<<T_TOK / 8, 256>>>(x, Wr);
    binning_kernel<<<1, 512>>>();

    // merged GEMMs: y = 64 shared tiles + 8*20 expert tiles = 224
    gemm_kernel<true><<<dim3(D_FF / 128, 224),     256, smem>>>(mask, out);
    gemm_kernel<false><<<dim3(D_MODEL / 128, 224), 256, smem>>>(mask, out);

    combine_kernel<<<T_TOK, 256>>>(mask, out);
}

// round 17
// speedup vs baseline: 1.2827x; 1.2827x over previous
#include <cuda_runtime.h>
#include <cuda_fp16.h>
#include <cstdint>

// ---------------- problem constants ----------------
#define T_TOK   8192
#define D_MODEL 1024
#define D_COND  256
#define D_IN    1280      // D_MODEL + D_COND
#define D_FF    4096
#define NEXP    8
#define TOPK    2
#define CAP     2560      // int(1.25 * 2 * 8192 / 8)
#define TKA     (T_TOK*TOPK)

typedef __half h16;

// ---------------- device scratch (static, no runtime allocation) ----------------
__device__ int   g_expert[TKA];
__device__ float g_weight[TKA];
__device__ int   g_slot[TKA];
__device__ int   g_route[NEXP*CAP];
__device__ int   g_cnt[NEXP];
__device__ float g_Y[(size_t)NEXP * CAP * D_MODEL];     // expert output (fp32)
__device__ h16 g_xh[(size_t)T_TOK * D_IN];              // fp16 [x|cond]
__device__ h16 g_Hsh[(size_t)T_TOK * D_FF];             // fp16 shared hidden
__device__ h16 g_Heh[(size_t)NEXP * CAP * D_FF];        // fp16 expert hidden
__device__ h16 g_W1sT[(size_t)D_FF * D_IN];             // fp16 W^T  [N][K]
__device__ h16 g_W2sT[(size_t)D_MODEL * D_FF];
__device__ h16 g_W1eT[(size_t)NEXP * D_FF * D_IN];
__device__ h16 g_W2eT[(size_t)NEXP * D_MODEL * D_FF];

// ---------------- helpers ----------------
__device__ __forceinline__ void cp16(void* dst_smem, const void* src_gmem) {
    unsigned sa = (unsigned)__cvta_generic_to_shared(dst_smem);
    asm volatile("cp.async.cg.shared.global [%0], [%1], 16;" :: "r"(sa), "l"(src_gmem));
}
__device__ __forceinline__ float gelu_f(float v) {
    // jax.nn.gelu (tanh form), HW tanh.approx
    float u = 0.7978845608028654f * (v + 0.044715f * v * v * v);
    float t;
    asm("tanh.approx.f32 %0, %1;" : "=f"(t) : "f"(u));
    return 0.5f * v * (1.0f + t);
}
#define MMA_F16(d, a, b) \
    asm volatile( \
        "mma.sync.aligned.m16n8k16.row.col.f32.f16.f16.f32 " \
        "{%0,%1,%2,%3}, {%4,%5,%6,%7}, {%8,%9}, {%0,%1,%2,%3};" \
        : "+f"((d)[0]), "+f"((d)[1]), "+f"((d)[2]), "+f"((d)[3]) \
        : "r"((a)[0]), "r"((a)[1]), "r"((a)[2]), "r"((a)[3]), \
          "r"((b)[0]), "r"((b)[1]))
#define LDSM4(r0, r1, r2, r3, addr) \
    asm volatile("ldmatrix.sync.aligned.m8n8.x4.shared.b16 {%0,%1,%2,%3}, [%4];" \
                 : "=r"(r0), "=r"(r1), "=r"(r2), "=r"(r3) : "r"(addr))

// ---------------- 0) prep: fused pack(x|cond->fp16) + transpose(all W -> fp16 [C][R]) ----
#define PACK_BLOCKS 10240
__global__ __launch_bounds__(256) void prep_kernel(const float* __restrict__ x,
                                                   const float* __restrict__ cond,
                                                   const float* __restrict__ W1s,
                                                   const float* __restrict__ W2s,
                                                   const float* __restrict__ W1e,
                                                   const float* __restrict__ W2e) {
    __shared__ float t[32][129];
    const int tid = threadIdx.x;
    int bid = blockIdx.x;

    if (bid < PACK_BLOCKS) {
        int i = bid * 256 + tid;               // float4 index; 320 per row
        int tok = i / 320, c4 = i % 320;
        float4 v;
        if (c4 < 256) v = ((const float4*)x)[(size_t)tok * 256 + c4];
        else          v = ((const float4*)cond)[(size_t)tok * 64 + (c4 - 256)];
        __half2 a = __floats2half2_rn(v.x, v.y);
        __half2 b = __floats2half2_rn(v.z, v.w);
        uint2 u = make_uint2(*(unsigned*)&a, *(unsigned*)&b);
        *(uint2*)(g_xh + (size_t)tok * D_IN + c4 * 4) = u;
        return;
    }
    bid -= PACK_BLOCKS;

    const float* src; h16* dst; int R, C;
    if (bid < 1280) {
        src = W1s; dst = g_W1sT; R = D_IN; C = D_FF;
    } else if (bid < 2304) {
        bid -= 1280; src = W2s; dst = g_W2sT; R = D_FF; C = D_MODEL;
    } else if (bid < 12544) {
        bid -= 2304; int e = bid / 1280; bid %= 1280;
        src = W1e + (size_t)e * D_IN * D_FF; dst = g_W1eT + (size_t)e * D_IN * D_FF;
        R = D_IN; C = D_FF;
    } else {
        bid -= 12544; int e = bid / 1024; bid %= 1024;
        src = W2e + (size_t)e * D_FF * D_MODEL; dst = g_W2eT + (size_t)e * D_FF * D_MODEL;
        R = D_FF; C = D_MODEL;
    }
    int tilesx = C / 128;
    int c0 = (bid % tilesx) * 128, r0 = (bid / tilesx) * 32;

    int row = tid >> 3, cq = tid & 7;
#pragma unroll
    for (int j = 0; j < 4; j++) {
        int c4i = (cq + 8 * j) * 4;
        float4 v = *(const float4*)(src + (size_t)(r0 + row) * C + c0 + c4i);
        t[row][c4i + 0] = v.x; t[row][c4i + 1] = v.y;
        t[row][c4i + 2] = v.z; t[row][c4i + 3] = v.w;
    }
    __syncthreads();

    int tx = tid & 31, iy = tid >> 5;
#pragma unroll
    for (int c = 0; c < 16; c++) {
        int i = iy + 8 * c;
        dst[(size_t)(c0 + i) * R + r0 + tx] = __float2half_rn(t[tx][i]);
    }
}

// ---------------- 1) router ----------------
__global__ __launch_bounds__(256) void router_kernel(const float* __restrict__ x,
                                                     const float* __restrict__ Wr) {
    __shared__ float sWr[D_MODEL * NEXP];
    const int tid = threadIdx.x;
    for (int i = tid; i < D_MODEL * NEXP; i += 256) sWr[i] = Wr[i];
    __syncthreads();

    const int warp = tid >> 5, lane = tid & 31;
    const int t = blockIdx.x * 8 + warp;
    const float* xr = x + (size_t)t * D_MODEL;

    float acc[NEXP];
#pragma unroll
    for (int e = 0; e < NEXP; e++) acc[e] = 0.f;
    for (int j = lane; j < D_MODEL; j += 32) {
        float xv = xr[j];
        const float* wrow = sWr + j * NEXP;
#pragma unroll
        for (int e = 0; e < NEXP; e++) acc[e] += xv * wrow[e];
    }
#pragma unroll
    for (int e = 0; e < NEXP; e++)
#pragma unroll
        for (int o = 16; o > 0; o >>= 1) acc[e] += __shfl_xor_sync(0xffffffffu, acc[e], o);

    if (lane == 0) {
        float mx = acc[0];
#pragma unroll
        for (int e = 1; e < NEXP; e++) mx = fmaxf(mx, acc[e]);
        float p[NEXP];
#pragma unroll
        for (int e = 0; e < NEXP; e++) p[e] = expf(acc[e] - mx);
        int i1 = 0; float v1 = p[0];
#pragma unroll
        for (int e = 1; e < NEXP; e++) if (p[e] > v1) { v1 = p[e]; i1 = e; }
        int i2 = -1; float v2 = -1.f;
#pragma unroll
        for (int e = 0; e < NEXP; e++) if (e != i1 && p[e] > v2) { v2 = p[e]; i2 = e; }
        float inv = 1.f / (v1 + v2);   // softmax denom cancels in normalization
        g_expert[2 * t]     = i1;  g_weight[2 * t]     = v1 * inv;
        g_expert[2 * t + 1] = i2;  g_weight[2 * t + 1] = v2 * inv;
    }
}

// ---------------- 2) binning: R12 semantics, packed-u64 counters ----------------
__global__ __launch_bounds__(512) void binning_kernel() {
    __shared__ int scnt[512 * NEXP];
    const int tid = threadIdx.x;
    for (int i = tid; i < NEXP * CAP; i += 512) g_route[i] = 0;

    const int base = tid * 32;           // 32 assignments per thread
    uint64_t c64 = 0;                    // 8 x 8-bit per-expert counters
#pragma unroll
    for (int i = 0; i < 32; i += 4) {
        int4 v = *(const int4*)(g_expert + base + i);
        c64 += (1ull << (v.x * 8)) + (1ull << (v.y * 8))
             + (1ull << (v.z * 8)) + (1ull << (v.w * 8));
    }
#pragma unroll
    for (int e = 0; e < NEXP; e++)
        scnt[tid * NEXP + e] = (int)((c64 >> (e * 8)) & 0xffull);
    __syncthreads();

    if (tid < NEXP) {
        int run = 0;
        for (int i = 0; i < 512; i++) {
            int v = scnt[i * NEXP + tid];
            scnt[i * NEXP + tid] = run;
            run += v;
        }
        g_cnt[tid] = min(run, CAP);
    }
    __syncthreads();

    uint64_t d64 = 0;
#pragma unroll
    for (int i = 0; i < 32; i += 4) {
        int4 v = *(const int4*)(g_expert + base + i);
        int es[4] = { v.x, v.y, v.z, v.w };
#pragma unroll
        for (int s = 0; s < 4; s++) {
            int e = es[s];
            int a = base + i + s;
            int pos = scnt[tid * NEXP + e] + (int)((d64 >> (e * 8)) & 0xffull);
            d64 += 1ull << (e * 8);
            if (pos < CAP) {
                int slot = e * CAP + pos;
                g_route[slot] = a >> 1;
                g_slot[a] = slot;
            } else {
                g_slot[a] = -1;
            }
        }
    }
}

// ---------------- 3) merged FP16 GEMM: 128 thr, 2x2 warps, 64x64 tile, ldmatrix ----
// L1=true : y<64 -> Hs = fp16(gelu(xc @ W1s)) ; y>=64 -> He = fp16(gelu(gather @ W1e))
// L1=false: y<64 -> out = mask/3 * (Hs @ W2s) ; y>=64 -> Y = He @ W2e
// 128x128 CTA tile, BK=32, 3-stage cp.async, 1 barrier/k-tile, ldmatrix.x4 frag loads.
#define STRB 40                      // smem row stride in halfs (32 data + 8 pad = 80B)
#define PLANE (128 * STRB)           // 5120 halfs = 10240 B
#define STAGE_ELE (2 * PLANE)        // A, B
#define STAGES 3
template <bool L1>
__global__ __launch_bounds__(128, 2) void gemm_kernel(const float* __restrict__ mask,
                                                      float* __restrict__ out) {
    constexpr int BM = 128, BK = 32;
    constexpr int KDIM = L1 ? D_IN : D_FF;
    constexpr int KT   = KDIM / BK;

    extern __shared__ h16 smem[];

    const int tid = threadIdx.x;
    const int n0 = blockIdx.x * 128;

    // ---- y-decode: shared tiles first, then expert tiles ----
    const int y = blockIdx.y;
    const bool sh = (y < 64);
    int e = 0, m0;
    if (sh) {
        m0 = y * BM;
    } else {
        int t = y - 64;
        e = t / 20;                      // 20 M-tiles per expert (CAP/128)
        m0 = (t % 20) * BM;
        if (m0 >= g_cnt[e]) return;      // uniform skip of empty tiles
    }

    const h16 *Ah, *Wh;
    if (L1) {
        Ah = g_xh;
        Wh = sh ? g_W1sT : (g_W1eT + (size_t)e * D_IN * D_FF);
    } else {
        Ah = sh ? g_Hsh : (g_Heh + (size_t)e * CAP * D_FF);
        Wh = sh ? g_W2sT : (g_W2eT + (size_t)e * D_FF * D_MODEL);
    }

    // ---- loader geometry: chunk (tid&3)*16B, row group tid>>2 (+32*i) ----
    const int chunk = tid & 3;
    const int rg    = tid >> 2;

    size_t aoff[4], boff[4];
#pragma unroll
    for (int i = 0; i < 4; i++) {
        int r = rg + 32 * i;
        int arow = (L1 && !sh) ? g_route[e * CAP + m0 + r] : (m0 + r);
        aoff[i] = (size_t)arow * KDIM + chunk * 8;
        boff[i] = (size_t)(n0 + r) * KDIM + chunk * 8;
    }

    auto load_tile = [&](int kt, int st) {
        const int k0 = kt * BK;
        h16* s = smem + st * STAGE_ELE;
#pragma unroll
        for (int i = 0; i < 4; i++) {
            int d = (rg + 32 * i) * STRB + chunk * 8;
            cp16(s + d,         Ah + aoff[i] + k0);
            cp16(s + PLANE + d, Wh + boff[i] + k0);
        }
        asm volatile("cp.async.commit_group;" ::: "memory");
    };

    const int warp = tid >> 5, lane = tid & 31;
    const int wm = warp >> 1, wn = warp & 1;   // 2x2 warp grid; warp tile 64x64
    const int lr = lane >> 2, lc = lane & 3;   // groupID, threadID-in-group

    float acc[4][8][4];
#pragma unroll
    for (int f = 0; f < 4; f++)
#pragma unroll
        for (int g = 0; g < 8; g++)
#pragma unroll
            for (int c = 0; c < 4; c++) acc[f][g][c] = 0.f;

    // ---- ldmatrix per-lane byte offsets (within a stage) ----
    // A tiles (16x16 per f): lanes 0-7 rows 0-7 klo | 8-15 rows 8-15 klo
    //                       | 16-23 rows 0-7 khi   | 24-31 rows 8-15 khi
    const int rA = (lane & 7) + ((lane >> 3) & 1) * 8;
    const int kA = (lane >> 4) * 16;                       // bytes
    // B tiles (16 n-rows x 16 k per g-pair): lanes 0-7 n0-7 klo | 8-15 n0-7 khi
    //                       | 16-23 n8-15 klo | 24-31 n8-15 khi
    const int rB = (lane & 7) + ((lane >> 4) & 1) * 8;
    const int kB = ((lane >> 3) & 1) * 16;                 // bytes
    const uint32_t aoffL = (uint32_t)((wm * 64 + rA) * STRB) * 2 + kA;
    const uint32_t boffL = (uint32_t)PLANE * 2 + (uint32_t)((wn * 64 + rB) * STRB) * 2 + kB;

    load_tile(0, 0);
    load_tile(1, 1);

    int cur = 0, nxt = 2;                  // slot of tile kt; slot for tile kt+2
    for (int kt = 0; kt < KT; kt++) {
        if (kt + 1 < KT) {
            asm volatile("cp.async.wait_group 1;" ::: "memory");
        } else {
            asm volatile("cp.async.wait_group 0;" ::: "memory");
        }
        __syncthreads();                   // tile kt visible; slot `nxt` fully drained
        if (kt + 2 < KT) load_tile(kt + 2, nxt);

        const uint32_t sb =
            (uint32_t)__cvta_generic_to_shared(smem + cur * STAGE_ELE);
        const uint32_t aL = sb + aoffL;
        const uint32_t bL = sb + boffL;

#pragma unroll
        for (int q = 0; q < 2; q++) {             // two k16 chunks per k-tile
            const int kq = q * 32;                // byte offset along k
            unsigned ah[4][4], bh[8][2];
#pragma unroll
            for (int f = 0; f < 4; f++)
                LDSM4(ah[f][0], ah[f][1], ah[f][2], ah[f][3],
                      aL + f * (16 * STRB * 2) + kq);
#pragma unroll
            for (int g2 = 0; g2 < 4; g2++)
                LDSM4(bh[2 * g2][0], bh[2 * g2][1], bh[2 * g2 + 1][0], bh[2 * g2 + 1][1],
                      bL + g2 * (16 * STRB * 2) + kq);
#pragma unroll
            for (int f = 0; f < 4; f++)
#pragma unroll
                for (int g = 0; g < 8; g++) MMA_F16(acc[f][g], ah[f], bh[g]);
        }
        cur = (cur == STAGES - 1) ? 0 : cur + 1;
        nxt = (nxt == STAGES - 1) ? 0 : nxt + 1;
    }

    // ---- epilogue ----
#pragma unroll
    for (int f = 0; f < 4; f++) {
        const int row = m0 + wm * 64 + f * 16 + lr;   // +8 for c2/c3
#pragma unroll
        for (int g = 0; g < 8; g++) {
            const int col = n0 + wn * 64 + g * 8 + 2 * lc;
            if (L1) {
                h16* dh = sh ? g_Hsh : (g_Heh + (size_t)e * CAP * D_FF);
                __half2 v0 = __floats2half2_rn(gelu_f(acc[f][g][0]), gelu_f(acc[f][g][1]));
                __half2 v1 = __floats2half2_rn(gelu_f(acc[f][g][2]), gelu_f(acc[f][g][3]));
                *(__half2*)(dh + (size_t)row * D_FF + col) = v0;
                *(__half2*)(dh + (size_t)(row + 8) * D_FF + col) = v1;
            } else if (sh) {
                float mk0 = mask[row] * (1.f / 3.f);
                float mk1 = mask[row + 8] * (1.f / 3.f);
                float2 v0 = make_float2(acc[f][g][0] * mk0, acc[f][g][1] * mk0);
                float2 v1 = make_float2(acc[f][g][2] * mk1, acc[f][g][3] * mk1);
                *(float2*)(out + (size_t)row * D_MODEL + col) = v0;
                *(float2*)(out + (size_t)(row + 8) * D_MODEL + col) = v1;
            } else {
                float* dst = g_Y + ((size_t)e * CAP + row) * D_MODEL;
                *(float2*)(dst + col) = make_float2(acc[f][g][0], acc[f][g][1]);
                *(float2*)(dst + (size_t)8 * D_MODEL + col) = make_float2(acc[f][g][2], acc[f][g][3]);
            }
        }
    }
}

// ---------------- 4) combine: out += (2/3)*mask*(w0*Y[s0] + w1*Y[s1]) ----------------
__global__ __launch_bounds__(256) void combine_kernel(const float* __restrict__ mask,
                                                      float* __restrict__ out) {
    const int idx = blockIdx.x * 256 + threadIdx.x;
    const int t = idx >> 8;
    const int c = (idx & 255) * 4;
    const int s0 = g_slot[2 * t], s1 = g_slot[2 * t + 1];
    const float w0 = g_weight[2 * t], w1 = g_weight[2 * t + 1];
    const float m = mask[t] * (2.f / 3.f);
    float ax = 0.f, ay = 0.f, az = 0.f, aw = 0.f;
    if (s0 >= 0) {
        float4 y = *(const float4*)(g_Y + (size_t)s0 * D_MODEL + c);
        ax += w0 * y.x; ay += w0 * y.y; az += w0 * y.z; aw += w0 * y.w;
    }
    if (s1 >= 0) {
        float4 y = *(const float4*)(g_Y + (size_t)s1 * D_MODEL + c);
        ax += w1 * y.x; ay += w1 * y.y; az += w1 * y.z; aw += w1 * y.w;
    }
    float4 o = *(float4*)(out + (size_t)t * D_MODEL + c);
    o.x += m * ax; o.y += m * ay; o.z += m * az; o.w += m * aw;
    *(float4*)(out + (size_t)t * D_MODEL + c) = o;
}

// ---------------- launch ----------------
extern "C" void kernel_launch(void* const* d_in, const int* in_sizes, int n_in,
                              void* d_out, int out_size) {
    const float* x    = (const float*)d_in[0];
    const float* cond = (const float*)d_in[1];
    const float* mask = (const float*)d_in[2];
    const float* Wr   = (const float*)d_in[3];
    const float* W1s  = (const float*)d_in[4];
    const float* W2s  = (const float*)d_in[5];
    const float* W1e  = (const float*)d_in[6];
    const float* W2e  = (const float*)d_in[7];
    float* out = (float*)d_out;

    const int smem = STAGES * STAGE_ELE * (int)sizeof(h16);   // 61440 B
    cudaFuncSetAttribute(gemm_kernel<true>,  cudaFuncAttributeMaxDynamicSharedMemorySize, smem);
    cudaFuncSetAttribute(gemm_kernel<false>, cudaFuncAttributeMaxDynamicSharedMemorySize, smem);

    // 3 launches before the GEMMs -> gemm<true> is this process's 4th launch (ncu slot)
    prep_kernel<<<30976, 256>>>(x, cond, W1s, W2s, W1e, W2e);
    router_kernel<<<T_TOK / 8, 256>>>(x, Wr);
    binning_kernel<<<1, 512>>>();

    // merged GEMMs: y = 64 shared tiles + 8*20 expert tiles = 224
    gemm_kernel<true><<<dim3(D_FF / 128, 224),     128, smem>>>(mask, out);
    gemm_kernel<false><<<dim3(D_MODEL / 128, 224), 128, smem>>>(mask, out);

    combine_kernel<<<T_TOK, 256>>>(mask, out);
}